// round 8
// baseline (speedup 1.0000x reference)
#include <cuda_runtime.h>
#include <cstdint>
#include <float.h>

// Problem constants
#define Bn 32768
#define Ln 4
#define Kn 2048
#define Dn 512

// Output layout (float32, flattened tuple in return order):
//   output [B,L], r [B,L,D], e [B,L,D], z_hat [B,D], count [1]
constexpr size_t OFF_OUT = 0;
constexpr size_t OFF_R   = (size_t)Bn * Ln;                       // 131072
constexpr size_t OFF_E   = OFF_R + (size_t)Bn * Ln * Dn;          // 67239936
constexpr size_t OFF_Z   = OFF_E + (size_t)Bn * Ln * Dn;          // 134348800
constexpr size_t OFF_CNT = OFF_Z + (size_t)Bn * Dn;               // 151126016

// Scratch (device globals; no allocations allowed)
__device__ int   g_idx[Bn * Ln];
__device__ int   g_hist[Ln * Kn];
__device__ float g_cnorm[Ln * Kn];
__device__ float g_xnorm[Bn];

// ---------------- packed f32x2 helpers ----------------
__device__ __forceinline__ unsigned long long pack2(float a, float b) {
    unsigned long long r;
    asm("mov.b64 %0, {%1, %2};" : "=l"(r) : "f"(a), "f"(b));
    return r;
}
__device__ __forceinline__ unsigned long long fma2(unsigned long long a,
                                                   unsigned long long b,
                                                   unsigned long long c) {
    unsigned long long d;
    asm("fma.rn.f32x2 %0, %1, %2, %3;" : "=l"(d) : "l"(a), "l"(b), "l"(c));
    return d;
}
__device__ __forceinline__ void unpack2(unsigned long long p, float& a, float& b) {
    asm("mov.b64 {%0, %1}, %2;" : "=f"(a), "=f"(b) : "l"(p));
}

// ---------------- XLA-GPU-style f32 row-norm of a 512-float row ----------------
// (passed bitwise in R3 — do not touch)
__device__ __forceinline__ float xla_rownorm512(const float* __restrict__ row,
                                                float* __restrict__ sh8) {
    int t = threadIdx.x;           // 0..255
    int lane = t & 31;
    int w = t >> 5;                // 0..7
    float2 e = *(const float2*)(row + 2 * t);
    float p = __fadd_rn(__fmul_rn(e.x, e.x), __fmul_rn(e.y, e.y));
#pragma unroll
    for (int off = 16; off; off >>= 1)
        p = __fadd_rn(p, __shfl_down_sync(0xFFFFFFFFu, p, off));
    if (lane == 0) sh8[w] = p;
    __syncthreads();
    float s = 0.0f;
    if (w == 0) {
        s = (lane < 8) ? sh8[lane] : 0.0f;
#pragma unroll
        for (int off = 16; off; off >>= 1)
            s = __fadd_rn(s, __shfl_down_sync(0xFFFFFFFFu, s, off));
    }
    return s;   // valid in thread 0 only
}

// ---------------- prep: codebook norms (XLA-order f32) + zero histogram ----------------
__global__ void __launch_bounds__(256) prep_kernel(const float* __restrict__ cb) {
    __shared__ float sh8[8];
    int code = blockIdx.x;                 // 0 .. L*K-1
    float s = xla_rownorm512(cb + (size_t)code * Dn, sh8);
    if (threadIdx.x == 0) {
        g_cnorm[code] = s;
        g_hist[code] = 0;
    }
}

// ---------------- per-level row norms (XLA-order f32) ----------------
__global__ void __launch_bounds__(256) xnorm_kernel(const float* __restrict__ out, int level) {
    __shared__ float sh8[8];
    int b = blockIdx.x;                    // 0 .. B-1
    float s = xla_rownorm512(out + OFF_R + ((size_t)b * Ln + level) * Dn, sh8);
    if (threadIdx.x == 0) g_xnorm[b] = s;
}

// ---------------- r[:,0,:] = x ----------------
__global__ void copy_r0_kernel(const float* __restrict__ x, float* __restrict__ out) {
    size_t t = (size_t)blockIdx.x * blockDim.x + threadIdx.x;  // B*D/4 threads
    int b = (int)(t >> 7);
    int d4 = ((int)t & 127) << 2;
    float4 v = *(const float4*)(x + (size_t)b * Dn + d4);
    *(float4*)(out + OFF_R + (size_t)b * Ln * Dn + d4) = v;
}

// ---------------- fused distance + argmin per level ----------------
constexpr int TM  = 128;   // rows per block
constexpr int TN  = 128;   // code chunk
constexpr int DKc = 8;     // D step per smem stage
constexpr int NIT = Dn / DKc;        // 64
constexpr int XSP_STRIDE = TM + 2;   // 130, ulonglong units (16B-aligned rows: 130*8=1040)
constexpr int CS_STRIDE  = TN + 4;   // 132 floats (16B-aligned rows: 132*4=528)

__global__ void __launch_bounds__(256, 2)
argmin_kernel(float* __restrict__ out_base, const float* __restrict__ cb, int level) {
    // x tile stored PRE-PACKED as {x,x} pairs -> LDS yields FMA2 operands directly
    __shared__ __align__(16) unsigned long long xsp[2][DKc * XSP_STRIDE]; // 2*8*130*8 = 16640 B
    __shared__ __align__(16) float              cs [2][DKc * CS_STRIDE];  // 2*8*132*4 =  8448 B

    const int tid = threadIdx.x;
    const int m0  = blockIdx.x * TM;
    const int tr  = tid & 15;          // row group: rows tr*8 .. tr*8+7
    const int tc  = tid >> 4;          // code group: codes tc*8 .. tc*8+7
    const int frow = tid >> 1;         // fill row/code 0..127
    const int fc4  = (tid & 1) << 2;   // fill col 0 or 4

    const float* __restrict__ cbl = cb + (size_t)level * Kn * Dn;
    const float* __restrict__ cn  = g_cnorm + level * Kn;
    const float* __restrict__ xrow = out_base + OFF_R + (size_t)level * Dn
                                   + ((size_t)(m0 + frow)) * (Ln * Dn) + fc4;

    float xn[8];
#pragma unroll
    for (int r = 0; r < 8; r++) xn[r] = g_xnorm[m0 + tr * 8 + r];

    float best[8];
    int   bidx[8];
#pragma unroll
    for (int r = 0; r < 8; r++) { best[r] = FLT_MAX; bidx[r] = 0; }

#pragma unroll 1
    for (int kc = 0; kc < Kn; kc += TN) {
        const float* __restrict__ crow = cbl + (size_t)(kc + frow) * Dn + fc4;

        unsigned long long acc[8][4];
#pragma unroll
        for (int r = 0; r < 8; r++)
#pragma unroll
            for (int p = 0; p < 4; p++) acc[r][p] = 0ULL;

        // ---- stage tile 0 + prefetch tile 1 ----
        float4 xg = *(const float4*)(xrow);
        float4 cg = *(const float4*)(crow);
        {
            unsigned long long* xd = &xsp[0][0];
            float* cd = &cs[0][0];
            xd[(fc4 + 0) * XSP_STRIDE + frow] = pack2(xg.x, xg.x);
            xd[(fc4 + 1) * XSP_STRIDE + frow] = pack2(xg.y, xg.y);
            xd[(fc4 + 2) * XSP_STRIDE + frow] = pack2(xg.z, xg.z);
            xd[(fc4 + 3) * XSP_STRIDE + frow] = pack2(xg.w, xg.w);
            cd[(fc4 + 0) * CS_STRIDE + frow] = cg.x;
            cd[(fc4 + 1) * CS_STRIDE + frow] = cg.y;
            cd[(fc4 + 2) * CS_STRIDE + frow] = cg.z;
            cd[(fc4 + 3) * CS_STRIDE + frow] = cg.w;
        }
        xg = *(const float4*)(xrow + DKc);
        cg = *(const float4*)(crow + DKc);
        __syncthreads();

#pragma unroll 1
        for (int it = 0; it < NIT; it++) {
            const int cur = it & 1;
            // store prefetched tile (it+1) into the other buffer (free since end of it-1)
            if (it + 1 < NIT) {
                unsigned long long* xd = &xsp[cur ^ 1][0];
                float* cd = &cs[cur ^ 1][0];
                xd[(fc4 + 0) * XSP_STRIDE + frow] = pack2(xg.x, xg.x);
                xd[(fc4 + 1) * XSP_STRIDE + frow] = pack2(xg.y, xg.y);
                xd[(fc4 + 2) * XSP_STRIDE + frow] = pack2(xg.z, xg.z);
                xd[(fc4 + 3) * XSP_STRIDE + frow] = pack2(xg.w, xg.w);
                cd[(fc4 + 0) * CS_STRIDE + frow] = cg.x;
                cd[(fc4 + 1) * CS_STRIDE + frow] = cg.y;
                cd[(fc4 + 2) * CS_STRIDE + frow] = cg.z;
                cd[(fc4 + 3) * CS_STRIDE + frow] = cg.w;
            }
            // prefetch tile (it+2)
            if (it + 2 < NIT) {
                xg = *(const float4*)(xrow + (it + 2) * DKc);
                cg = *(const float4*)(crow + (it + 2) * DKc);
            }
            // compute on current buffer: 8 kk x (8 rows x 8 codes)
#pragma unroll
            for (int kk = 0; kk < DKc; kk++) {
                const unsigned long long* xp = &xsp[cur][kk * XSP_STRIDE + tr * 8];
                ulonglong2 xv01 = *(const ulonglong2*)(xp + 0);
                ulonglong2 xv23 = *(const ulonglong2*)(xp + 2);
                ulonglong2 xv45 = *(const ulonglong2*)(xp + 4);
                ulonglong2 xv67 = *(const ulonglong2*)(xp + 6);
                const float* cp = &cs[cur][kk * CS_STRIDE + tc * 8];
                ulonglong2 cc01 = *(const ulonglong2*)(cp + 0);
                ulonglong2 cc23 = *(const ulonglong2*)(cp + 4);
                acc[0][0] = fma2(xv01.x, cc01.x, acc[0][0]);
                acc[0][1] = fma2(xv01.x, cc01.y, acc[0][1]);
                acc[0][2] = fma2(xv01.x, cc23.x, acc[0][2]);
                acc[0][3] = fma2(xv01.x, cc23.y, acc[0][3]);
                acc[1][0] = fma2(xv01.y, cc01.x, acc[1][0]);
                acc[1][1] = fma2(xv01.y, cc01.y, acc[1][1]);
                acc[1][2] = fma2(xv01.y, cc23.x, acc[1][2]);
                acc[1][3] = fma2(xv01.y, cc23.y, acc[1][3]);
                acc[2][0] = fma2(xv23.x, cc01.x, acc[2][0]);
                acc[2][1] = fma2(xv23.x, cc01.y, acc[2][1]);
                acc[2][2] = fma2(xv23.x, cc23.x, acc[2][2]);
                acc[2][3] = fma2(xv23.x, cc23.y, acc[2][3]);
                acc[3][0] = fma2(xv23.y, cc01.x, acc[3][0]);
                acc[3][1] = fma2(xv23.y, cc01.y, acc[3][1]);
                acc[3][2] = fma2(xv23.y, cc23.x, acc[3][2]);
                acc[3][3] = fma2(xv23.y, cc23.y, acc[3][3]);
                acc[4][0] = fma2(xv45.x, cc01.x, acc[4][0]);
                acc[4][1] = fma2(xv45.x, cc01.y, acc[4][1]);
                acc[4][2] = fma2(xv45.x, cc23.x, acc[4][2]);
                acc[4][3] = fma2(xv45.x, cc23.y, acc[4][3]);
                acc[5][0] = fma2(xv45.y, cc01.x, acc[5][0]);
                acc[5][1] = fma2(xv45.y, cc01.y, acc[5][1]);
                acc[5][2] = fma2(xv45.y, cc23.x, acc[5][2]);
                acc[5][3] = fma2(xv45.y, cc23.y, acc[5][3]);
                acc[6][0] = fma2(xv67.x, cc01.x, acc[6][0]);
                acc[6][1] = fma2(xv67.x, cc01.y, acc[6][1]);
                acc[6][2] = fma2(xv67.x, cc23.x, acc[6][2]);
                acc[6][3] = fma2(xv67.x, cc23.y, acc[6][3]);
                acc[7][0] = fma2(xv67.y, cc01.x, acc[7][0]);
                acc[7][1] = fma2(xv67.y, cc01.y, acc[7][1]);
                acc[7][2] = fma2(xv67.y, cc23.x, acc[7][2]);
                acc[7][3] = fma2(xv67.y, cc23.y, acc[7][3]);
            }
            __syncthreads();
        }

        // fold chunk scores: d = fl( fl(xx - fl(2*m)) + cc ), first-index tie-break
#pragma unroll
        for (int p = 0; p < 4; p++) {
            int k0 = kc + tc * 8 + 2 * p;
            float2 cnv = *(const float2*)(cn + k0);
#pragma unroll
            for (int r = 0; r < 8; r++) {
                float m0v, m1v;
                unpack2(acc[r][p], m0v, m1v);
                float v0 = __fadd_rn(__fsub_rn(xn[r], __fmul_rn(2.0f, m0v)), cnv.x);
                float v1 = __fadd_rn(__fsub_rn(xn[r], __fmul_rn(2.0f, m1v)), cnv.y);
                if (v0 < best[r]) { best[r] = v0; bidx[r] = k0; }
                if (v1 < best[r]) { best[r] = v1; bidx[r] = k0 + 1; }
            }
        }
    }

    // cross-thread reduction: 128 rows x 16 candidates
    __syncthreads();
    float* rv = (float*)&xsp[0][0];    // 2048 floats (fits in 16640 B)
    int*   ri = (int*)&cs[0][0];       // 2048 ints  (fits in  8448 B)
#pragma unroll
    for (int r = 0; r < 8; r++) {
        rv[(tr * 8 + r) * 16 + tc] = best[r];
        ri[(tr * 8 + r) * 16 + tc] = bidx[r];
    }
    __syncthreads();
    if (tid < TM) {
        float bv = rv[tid * 16];
        int bi = ri[tid * 16];
#pragma unroll
        for (int j = 1; j < 16; j++) {
            float v = rv[tid * 16 + j];
            int i2 = ri[tid * 16 + j];
            if (v < bv || (v == bv && i2 < bi)) { bv = v; bi = i2; }
        }
        int b = m0 + tid;
        g_idx[b * Ln + level] = bi;
        out_base[OFF_OUT + (size_t)b * Ln + level] = (float)bi;
        atomicAdd(&g_hist[level * Kn + bi], 1);
    }
}

// ---------------- gather e, compute next residual ----------------
__global__ void update_kernel(const float* __restrict__ cb, float* __restrict__ out, int level) {
    size_t t = (size_t)blockIdx.x * 256 + threadIdx.x;   // B*D/4
    int b = (int)(t >> 7);
    int d4 = ((int)t & 127) << 2;
    int idx = g_idx[b * Ln + level];
    const float* cbl = cb + ((size_t)level * Kn + idx) * Dn;
    float4 e = *(const float4*)(cbl + d4);
    size_t ro = ((size_t)b * Ln + level) * Dn + d4;
    *(float4*)(out + OFF_E + ro) = e;
    if (level < Ln - 1) {
        float4 r = *(const float4*)(out + OFF_R + ro);
        float4 rn = make_float4(__fsub_rn(r.x, e.x), __fsub_rn(r.y, e.y),
                                __fsub_rn(r.z, e.z), __fsub_rn(r.w, e.w));
        *(float4*)(out + OFF_R + ro + Dn) = rn;
    }
}

// ---------------- z_hat = x + (sum_l e_l - x) ----------------
__global__ void zhat_kernel(const float* __restrict__ x, float* __restrict__ out) {
    size_t t = (size_t)blockIdx.x * 256 + threadIdx.x;   // B*D/4
    int b = (int)(t >> 7);
    int d4 = ((int)t & 127) << 2;
    const float* eb = out + OFF_E + (size_t)b * Ln * Dn + d4;
    float4 e0 = *(const float4*)(eb);
    float4 e1 = *(const float4*)(eb + Dn);
    float4 e2 = *(const float4*)(eb + 2 * Dn);
    float4 e3 = *(const float4*)(eb + 3 * Dn);
    float4 xv = *(const float4*)(x + (size_t)b * Dn + d4);
    float4 z;
    z.x = __fadd_rn(xv.x, __fsub_rn(__fadd_rn(__fadd_rn(__fadd_rn(e0.x, e1.x), e2.x), e3.x), xv.x));
    z.y = __fadd_rn(xv.y, __fsub_rn(__fadd_rn(__fadd_rn(__fadd_rn(e0.y, e1.y), e2.y), e3.y), xv.y));
    z.z = __fadd_rn(xv.z, __fsub_rn(__fadd_rn(__fadd_rn(__fadd_rn(e0.z, e1.z), e2.z), e3.z), xv.z));
    z.w = __fadd_rn(xv.w, __fsub_rn(__fadd_rn(__fadd_rn(__fadd_rn(e0.w, e1.w), e2.w), e3.w), xv.w));
    *(float4*)(out + OFF_Z + (size_t)b * Dn + d4) = z;
}

// ---------------- unused-code count ----------------
__global__ void count_kernel(float* __restrict__ out) {
    int t = threadIdx.x;   // 256
    int c = 0;
    for (int i = t; i < Ln * Kn; i += 256)
        if (g_hist[i] == 0) c++;
    for (int o = 16; o; o >>= 1) c += __shfl_down_sync(0xFFFFFFFFu, c, o);
    __shared__ int ws[8];
    if ((t & 31) == 0) ws[t >> 5] = c;
    __syncthreads();
    if (t == 0) {
        int tot = 0;
        for (int j = 0; j < 8; j++) tot += ws[j];
        out[OFF_CNT] = (float)tot;
    }
}

extern "C" void kernel_launch(void* const* d_in, const int* in_sizes, int n_in,
                              void* d_out, int out_size) {
    const float* x  = (const float*)d_in[0];   // [B, D]
    const float* cb = (const float*)d_in[1];   // [L, K, D]
    float* out = (float*)d_out;

    prep_kernel<<<Ln * Kn, 256>>>(cb);
    copy_r0_kernel<<<(Bn * Dn / 4) / 256, 256>>>(x, out);
    for (int l = 0; l < Ln; l++) {
        xnorm_kernel<<<Bn, 256>>>(out, l);
        argmin_kernel<<<Bn / TM, 256>>>(out, cb, l);
        update_kernel<<<(Bn * Dn / 4) / 256, 256>>>(cb, out, l);
    }
    zhat_kernel<<<(Bn * Dn / 4) / 256, 256>>>(x, out);
    count_kernel<<<1, 256>>>(out);
}

// round 9
// speedup vs baseline: 6.5411x; 6.5411x over previous
#include <cuda_runtime.h>
#include <cuda_bf16.h>
#include <cstdint>
#include <float.h>

#define Bn 32768
#define Ln 4
#define Kn 2048
#define Dn 512

constexpr size_t OFF_OUT = 0;
constexpr size_t OFF_R   = (size_t)Bn * Ln;
constexpr size_t OFF_E   = OFF_R + (size_t)Bn * Ln * Dn;
constexpr size_t OFF_Z   = OFF_E + (size_t)Bn * Ln * Dn;
constexpr size_t OFF_CNT = OFF_Z + (size_t)Bn * Dn;

// Scratch (device globals; allocations forbidden)
__device__ int   g_idx[Bn * Ln];
__device__ int   g_hist[Ln * Kn];
__device__ float g_cnorm[Ln * Kn];
__device__ float g_xnorm[Bn];
__device__ float g_cnmax[Ln];
__device__ __nv_bfloat16 g_cbh[(size_t)Ln * Kn * Dn];   // 8 MB
__device__ __nv_bfloat16 g_xh[(size_t)Bn * Dn];         // 32 MB
__device__ float g_sc[(size_t)Bn * Kn];                 // 256 MB approx scores

__device__ __forceinline__ uint32_t sptr(const void* p) {
    return (uint32_t)__cvta_generic_to_shared(p);
}

// ---------------- XLA-GPU-style f32 row-norm (bitwise-proven R3 — do not touch) ----------------
__device__ __forceinline__ float xla_rownorm512(const float* __restrict__ row,
                                                float* __restrict__ sh8) {
    int t = threadIdx.x;           // 0..255
    int lane = t & 31;
    int w = t >> 5;
    float2 e = *(const float2*)(row + 2 * t);
    float p = __fadd_rn(__fmul_rn(e.x, e.x), __fmul_rn(e.y, e.y));
#pragma unroll
    for (int off = 16; off; off >>= 1)
        p = __fadd_rn(p, __shfl_down_sync(0xFFFFFFFFu, p, off));
    if (lane == 0) sh8[w] = p;
    __syncthreads();
    float s = 0.0f;
    if (w == 0) {
        s = (lane < 8) ? sh8[lane] : 0.0f;
#pragma unroll
        for (int off = 16; off; off >>= 1)
            s = __fadd_rn(s, __shfl_down_sync(0xFFFFFFFFu, s, off));
    }
    return s;
}

__global__ void init_kernel() {
    if (threadIdx.x < Ln) g_cnmax[threadIdx.x] = 0.0f;
}

// ---------------- prep: cnorm (XLA order) + hist zero + bf16 codebook + cnmax ----------------
__global__ void __launch_bounds__(256) prep_kernel(const float* __restrict__ cb) {
    __shared__ float sh8[8];
    int code = blockIdx.x;                 // 0 .. L*K-1
    const float* row = cb + (size_t)code * Dn;
    float s = xla_rownorm512(row, sh8);
    if (threadIdx.x == 0) {
        g_cnorm[code] = s;
        g_hist[code] = 0;
        atomicMax((int*)&g_cnmax[code / Kn], __float_as_int(s));
    }
    int d = threadIdx.x * 2;
    float2 v = *(const float2*)(row + d);
    __nv_bfloat162 bv;
    bv.x = __float2bfloat16_rn(v.x);
    bv.y = __float2bfloat16_rn(v.y);
    *(__nv_bfloat162*)(g_cbh + (size_t)code * Dn + d) = bv;
}

// ---------------- per-level row norms ----------------
__global__ void __launch_bounds__(256) xnorm_kernel(const float* __restrict__ out, int level) {
    __shared__ float sh8[8];
    int b = blockIdx.x;
    float s = xla_rownorm512(out + OFF_R + ((size_t)b * Ln + level) * Dn, sh8);
    if (threadIdx.x == 0) g_xnorm[b] = s;
}

// ---------------- r[:,0,:] = x ----------------
__global__ void copy_r0_kernel(const float* __restrict__ x, float* __restrict__ out) {
    size_t t = (size_t)blockIdx.x * blockDim.x + threadIdx.x;
    int b = (int)(t >> 7);
    int d4 = ((int)t & 127) << 2;
    float4 v = *(const float4*)(x + (size_t)b * Dn + d4);
    *(float4*)(out + OFF_R + (size_t)b * Ln * Dn + d4) = v;
}

// ---------------- convert residual level l to bf16 ----------------
__global__ void convx_kernel(const float* __restrict__ out, int level) {
    size_t t = (size_t)blockIdx.x * 256 + threadIdx.x;   // B*D/8 threads
    int b = (int)(t >> 6);
    int d8 = ((int)t & 63) << 3;
    const float* src = out + OFF_R + ((size_t)b * Ln + level) * Dn + d8;
    float4 v0 = *(const float4*)(src);
    float4 v1 = *(const float4*)(src + 4);
    __nv_bfloat162 o[4];
    o[0].x = __float2bfloat16_rn(v0.x); o[0].y = __float2bfloat16_rn(v0.y);
    o[1].x = __float2bfloat16_rn(v0.z); o[1].y = __float2bfloat16_rn(v0.w);
    o[2].x = __float2bfloat16_rn(v1.x); o[2].y = __float2bfloat16_rn(v1.y);
    o[3].x = __float2bfloat16_rn(v1.z); o[3].y = __float2bfloat16_rn(v1.w);
    *(uint4*)(g_xh + (size_t)b * Dn + d8) = *(uint4*)o;
}

// ---------------- approximate score GEMM: t~ = cn - 2*(x~ . c~) ----------------
// Block: 128 rows x 128 codes, 8 warps (2x4), warp tile 64x32, k-step 16.
constexpr int ASTR = 24;   // smem row stride in bf16 (48B: conflict-free ldmatrix)

__global__ void __launch_bounds__(256)
gemm_kernel(int level) {
    __shared__ __align__(16) __nv_bfloat16 as[2][128 * ASTR];
    __shared__ __align__(16) __nv_bfloat16 bs[2][128 * ASTR];

    const int tid = threadIdx.x;
    const int lane = tid & 31;
    const int wid = tid >> 5;
    const int warp_m = wid >> 2;       // 0..1
    const int warp_n = wid & 3;        // 0..3
    const int m0 = blockIdx.y * 128;
    const int n0 = blockIdx.x * 128;

    const __nv_bfloat16* __restrict__ Ag = g_xh + (size_t)m0 * Dn;
    const __nv_bfloat16* __restrict__ Bg = g_cbh + ((size_t)level * Kn + n0) * Dn;

    // fill indexing: thread t loads 8 bf16 (16B): row = t>>1, half = t&1
    const int frow = tid >> 1;
    const int fhalf = (tid & 1) << 3;

    // ldmatrix lane addressing
    const int arow = (lane & 7) + ((lane >> 3) & 1) * 8;
    const int acol = (lane >> 4) << 3;
    const int brow = lane & 7;
    const int bcol = ((lane >> 3) & 1) << 3;

    float acc[4][4][4];
#pragma unroll
    for (int i = 0; i < 4; i++)
#pragma unroll
        for (int j = 0; j < 4; j++)
#pragma unroll
            for (int r = 0; r < 4; r++) acc[i][j][r] = 0.0f;

    // stage k-step 0
    uint4 av = *(const uint4*)(Ag + (size_t)frow * Dn + fhalf);
    uint4 bv = *(const uint4*)(Bg + (size_t)frow * Dn + fhalf);
    *(uint4*)(as[0] + frow * ASTR + fhalf) = av;
    *(uint4*)(bs[0] + frow * ASTR + fhalf) = bv;
    __syncthreads();

#pragma unroll 1
    for (int ks = 0; ks < Dn / 16; ks++) {
        const int cur = ks & 1;
        if (ks + 1 < Dn / 16) {
            av = *(const uint4*)(Ag + (size_t)frow * Dn + (ks + 1) * 16 + fhalf);
            bv = *(const uint4*)(Bg + (size_t)frow * Dn + (ks + 1) * 16 + fhalf);
        }
        uint32_t a[4][4], b[4][2];
#pragma unroll
        for (int mt = 0; mt < 4; mt++) {
            uint32_t ad = sptr(as[cur] + (warp_m * 64 + mt * 16 + arow) * ASTR + acol);
            asm volatile("ldmatrix.sync.aligned.m8n8.x4.shared.b16 {%0,%1,%2,%3}, [%4];"
                         : "=r"(a[mt][0]), "=r"(a[mt][1]), "=r"(a[mt][2]), "=r"(a[mt][3])
                         : "r"(ad));
        }
#pragma unroll
        for (int nt = 0; nt < 4; nt++) {
            uint32_t bd = sptr(bs[cur] + (warp_n * 32 + nt * 8 + brow) * ASTR + bcol);
            asm volatile("ldmatrix.sync.aligned.m8n8.x2.shared.b16 {%0,%1}, [%2];"
                         : "=r"(b[nt][0]), "=r"(b[nt][1])
                         : "r"(bd));
        }
#pragma unroll
        for (int mt = 0; mt < 4; mt++)
#pragma unroll
            for (int nt = 0; nt < 4; nt++) {
                asm volatile(
                    "mma.sync.aligned.m16n8k16.row.col.f32.bf16.bf16.f32 "
                    "{%0,%1,%2,%3}, {%4,%5,%6,%7}, {%8,%9}, {%0,%1,%2,%3};"
                    : "+f"(acc[mt][nt][0]), "+f"(acc[mt][nt][1]),
                      "+f"(acc[mt][nt][2]), "+f"(acc[mt][nt][3])
                    : "r"(a[mt][0]), "r"(a[mt][1]), "r"(a[mt][2]), "r"(a[mt][3]),
                      "r"(b[nt][0]), "r"(b[nt][1]));
            }
        if (ks + 1 < Dn / 16) {
            *(uint4*)(as[cur ^ 1] + frow * ASTR + fhalf) = av;
            *(uint4*)(bs[cur ^ 1] + frow * ASTR + fhalf) = bv;
        }
        __syncthreads();
    }

    // epilogue: t~ = cn - 2*m~   (approximate only)
    const float* __restrict__ cn = g_cnorm + level * Kn;
    const int g = lane >> 2;
    const int tq = lane & 3;
#pragma unroll
    for (int mt = 0; mt < 4; mt++) {
#pragma unroll
        for (int nt = 0; nt < 4; nt++) {
            int col = n0 + warp_n * 32 + nt * 8 + tq * 2;
            float2 cnv = *(const float2*)(cn + col - n0 + n0);   // cn[col]
            int r0 = m0 + warp_m * 64 + mt * 16 + g;
            float2 o0, o1;
            o0.x = fmaf(-2.0f, acc[mt][nt][0], cnv.x);
            o0.y = fmaf(-2.0f, acc[mt][nt][1], cnv.y);
            o1.x = fmaf(-2.0f, acc[mt][nt][2], cnv.x);
            o1.y = fmaf(-2.0f, acc[mt][nt][3], cnv.y);
            *(float2*)(g_sc + (size_t)r0 * Kn + col) = o0;
            *(float2*)(g_sc + (size_t)(r0 + 8) * Kn + col) = o1;
        }
    }
}

// ---------------- select: min + candidate collect + exact rescore ----------------
constexpr int CAP = 64;

__global__ void __launch_bounds__(256)
select_kernel(float* __restrict__ out_base, const float* __restrict__ cb, int level) {
    __shared__ int cand[8][CAP];
    const int lane = threadIdx.x & 31;
    const int wid = threadIdx.x >> 5;
    const int b = blockIdx.x * 8 + wid;

    const float* __restrict__ srow = g_sc + (size_t)b * Kn;
    const float* __restrict__ cnl = g_cnorm + level * Kn;
    const float* __restrict__ cbl = cb + (size_t)level * Kn * Dn;
    const float* __restrict__ xr = out_base + OFF_R + ((size_t)b * Ln + level) * Dn;
    const float xn = g_xnorm[b];

    // pass 1: min approx score
    float vmin = FLT_MAX;
#pragma unroll 4
    for (int c = 0; c < Kn / 32; c++) {
        float v = srow[c * 32 + lane];
        vmin = fminf(vmin, v);
    }
#pragma unroll
    for (int off = 16; off; off >>= 1)
        vmin = fminf(vmin, __shfl_xor_sync(0xFFFFFFFFu, vmin, off));

    // rigorous candidate threshold
    float delta = 0.032f * sqrtf(xn * g_cnmax[level]) + 0.5f;
    float T = vmin + delta;

    // pass 2: ordered candidate collection
    int cnt = 0;
    for (int c = 0; c < Kn / 32; c++) {
        float v = srow[c * 32 + lane];
        bool p = (v <= T);
        unsigned mask = __ballot_sync(0xFFFFFFFFu, p);
        int pos = cnt + __popc(mask & ((1u << lane) - 1u));
        if (p && pos < CAP) cand[wid][pos] = c * 32 + lane;
        cnt += __popc(mask);
    }
    bool ovf = (cnt > CAP);
    int n_items = ovf ? Kn : cnt;

    // exact rescore (bitwise R3 chain): m = sequential FMA over ascending d
    float bv = FLT_MAX;
    int bk = 0x7FFFFFFF;
    for (int j = lane; j < n_items; j += 32) {
        int k = ovf ? j : cand[wid][j];
        const float* cr = cbl + (size_t)k * Dn;
        float m = 0.0f;
#pragma unroll 8
        for (int d = 0; d < Dn; d++) m = __fmaf_rn(xr[d], cr[d], m);
        float v = __fadd_rn(__fsub_rn(xn, __fmul_rn(2.0f, m)), cnl[k]);
        if (v < bv || (v == bv && k < bk)) { bv = v; bk = k; }
    }
#pragma unroll
    for (int off = 16; off; off >>= 1) {
        float ov = __shfl_down_sync(0xFFFFFFFFu, bv, off);
        int ok = __shfl_down_sync(0xFFFFFFFFu, bk, off);
        if (ov < bv || (ov == bv && ok < bk)) { bv = ov; bk = ok; }
    }
    if (lane == 0) {
        g_idx[b * Ln + level] = bk;
        out_base[OFF_OUT + (size_t)b * Ln + level] = (float)bk;
        atomicAdd(&g_hist[level * Kn + bk], 1);
    }
}

// ---------------- gather e, compute next residual ----------------
__global__ void update_kernel(const float* __restrict__ cb, float* __restrict__ out, int level) {
    size_t t = (size_t)blockIdx.x * 256 + threadIdx.x;   // B*D/4
    int b = (int)(t >> 7);
    int d4 = ((int)t & 127) << 2;
    int idx = g_idx[b * Ln + level];
    const float* cbl = cb + ((size_t)level * Kn + idx) * Dn;
    float4 e = *(const float4*)(cbl + d4);
    size_t ro = ((size_t)b * Ln + level) * Dn + d4;
    *(float4*)(out + OFF_E + ro) = e;
    if (level < Ln - 1) {
        float4 r = *(const float4*)(out + OFF_R + ro);
        float4 rn = make_float4(__fsub_rn(r.x, e.x), __fsub_rn(r.y, e.y),
                                __fsub_rn(r.z, e.z), __fsub_rn(r.w, e.w));
        *(float4*)(out + OFF_R + ro + Dn) = rn;
    }
}

// ---------------- z_hat ----------------
__global__ void zhat_kernel(const float* __restrict__ x, float* __restrict__ out) {
    size_t t = (size_t)blockIdx.x * 256 + threadIdx.x;   // B*D/4
    int b = (int)(t >> 7);
    int d4 = ((int)t & 127) << 2;
    const float* eb = out + OFF_E + (size_t)b * Ln * Dn + d4;
    float4 e0 = *(const float4*)(eb);
    float4 e1 = *(const float4*)(eb + Dn);
    float4 e2 = *(const float4*)(eb + 2 * Dn);
    float4 e3 = *(const float4*)(eb + 3 * Dn);
    float4 xv = *(const float4*)(x + (size_t)b * Dn + d4);
    float4 z;
    z.x = __fadd_rn(xv.x, __fsub_rn(__fadd_rn(__fadd_rn(__fadd_rn(e0.x, e1.x), e2.x), e3.x), xv.x));
    z.y = __fadd_rn(xv.y, __fsub_rn(__fadd_rn(__fadd_rn(__fadd_rn(e0.y, e1.y), e2.y), e3.y), xv.y));
    z.z = __fadd_rn(xv.z, __fsub_rn(__fadd_rn(__fadd_rn(__fadd_rn(e0.z, e1.z), e2.z), e3.z), xv.z));
    z.w = __fadd_rn(xv.w, __fsub_rn(__fadd_rn(__fadd_rn(__fadd_rn(e0.w, e1.w), e2.w), e3.w), xv.w));
    *(float4*)(out + OFF_Z + (size_t)b * Dn + d4) = z;
}

// ---------------- unused-code count ----------------
__global__ void count_kernel(float* __restrict__ out) {
    int t = threadIdx.x;   // 256
    int c = 0;
    for (int i = t; i < Ln * Kn; i += 256)
        if (g_hist[i] == 0) c++;
    for (int o = 16; o; o >>= 1) c += __shfl_down_sync(0xFFFFFFFFu, c, o);
    __shared__ int ws[8];
    if ((t & 31) == 0) ws[t >> 5] = c;
    __syncthreads();
    if (t == 0) {
        int tot = 0;
        for (int j = 0; j < 8; j++) tot += ws[j];
        out[OFF_CNT] = (float)tot;
    }
}

extern "C" void kernel_launch(void* const* d_in, const int* in_sizes, int n_in,
                              void* d_out, int out_size) {
    const float* x  = (const float*)d_in[0];   // [B, D]
    const float* cb = (const float*)d_in[1];   // [L, K, D]
    float* out = (float*)d_out;

    init_kernel<<<1, 32>>>();
    prep_kernel<<<Ln * Kn, 256>>>(cb);
    copy_r0_kernel<<<(Bn * Dn / 4) / 256, 256>>>(x, out);
    for (int l = 0; l < Ln; l++) {
        xnorm_kernel<<<Bn, 256>>>(out, l);
        convx_kernel<<<(Bn * Dn / 8) / 256, 256>>>(out, l);
        gemm_kernel<<<dim3(Kn / 128, Bn / 128), 256>>>(l);
        select_kernel<<<Bn / 8, 256>>>(out, cb, l);
        update_kernel<<<(Bn * Dn / 4) / 256, 256>>>(cb, out, l);
    }
    zhat_kernel<<<(Bn * Dn / 4) / 256, 256>>>(x, out);
    count_kernel<<<1, 256>>>(out);
}

// round 11
// speedup vs baseline: 7.0137x; 1.0722x over previous
#include <cuda_runtime.h>
#include <cuda_bf16.h>
#include <cuda_fp16.h>
#include <cstdint>
#include <float.h>

#define Bn 32768
#define Ln 4
#define Kn 2048
#define Dn 512

constexpr size_t OFF_OUT = 0;
constexpr size_t OFF_R   = (size_t)Bn * Ln;
constexpr size_t OFF_E   = OFF_R + (size_t)Bn * Ln * Dn;
constexpr size_t OFF_Z   = OFF_E + (size_t)Bn * Ln * Dn;
constexpr size_t OFF_CNT = OFF_Z + (size_t)Bn * Dn;

// Scratch (device globals; allocations forbidden)
__device__ int    g_idx[Bn * Ln];
__device__ int    g_hist[Ln * Kn];
__device__ float  g_cnorm[Ln * Kn];
__device__ float  g_xnorm[Bn];
__device__ float  g_cnmax[Ln];
__device__ float  g_bmin[(size_t)Bn * 16];              // per-(row, n-block) min
__device__ __nv_bfloat16 g_cbh[(size_t)Ln * Kn * Dn];   // 8 MB
__device__ __nv_bfloat16 g_xh[(size_t)Bn * Dn];         // 32 MB
__device__ __half g_sch[(size_t)Bn * Kn];               // 128 MB f16 approx scores

__device__ __forceinline__ uint32_t sptr(const void* p) {
    return (uint32_t)__cvta_generic_to_shared(p);
}
__device__ __forceinline__ void cpa16(uint32_t d, const void* s) {
    asm volatile("cp.async.ca.shared.global [%0], [%1], 16;" :: "r"(d), "l"(s));
}

// ---- XLA-bitwise 512-row-norm tail: thread t holds p = fl(x[2t]^2 + x[2t+1]^2) ----
__device__ __forceinline__ float xla_norm_tail(float p, float* sh8) {
    int t = threadIdx.x, lane = t & 31, w = t >> 5;
#pragma unroll
    for (int off = 16; off; off >>= 1)
        p = __fadd_rn(p, __shfl_down_sync(0xFFFFFFFFu, p, off));
    if (lane == 0) sh8[w] = p;
    __syncthreads();
    float s = 0.0f;
    if (w == 0) {
        s = (lane < 8) ? sh8[lane] : 0.0f;
#pragma unroll
        for (int off = 16; off; off >>= 1)
            s = __fadd_rn(s, __shfl_down_sync(0xFFFFFFFFu, s, off));
    }
    return s;   // valid in thread 0
}

__global__ void init_kernel() {
    if (threadIdx.x < Ln) g_cnmax[threadIdx.x] = 0.0f;
}

// ---------------- prep: cnorm (XLA order) + hist zero + bf16 codebook + cnmax ----------------
__global__ void __launch_bounds__(256) prep_kernel(const float* __restrict__ cb) {
    __shared__ float sh8[8];
    int code = blockIdx.x;                 // 0 .. L*K-1
    const float* row = cb + (size_t)code * Dn;
    float2 e = *(const float2*)(row + 2 * threadIdx.x);
    float p = __fadd_rn(__fmul_rn(e.x, e.x), __fmul_rn(e.y, e.y));
    float s = xla_norm_tail(p, sh8);
    if (threadIdx.x == 0) {
        g_cnorm[code] = s;
        g_hist[code] = 0;
        atomicMax((int*)&g_cnmax[code / Kn], __float_as_int(s));
    }
    __nv_bfloat162 bv;
    bv.x = __float2bfloat16_rn(e.x);
    bv.y = __float2bfloat16_rn(e.y);
    *(__nv_bfloat162*)(g_cbh + (size_t)code * Dn + 2 * threadIdx.x) = bv;
}

// ---------------- r[:,0,:] = x ; bf16 x ; xnorm level 0 ----------------
__global__ void __launch_bounds__(256) copy_r0_kernel(const float* __restrict__ x,
                                                      float* __restrict__ out) {
    __shared__ float sh8[8];
    int b = blockIdx.x;
    int t = threadIdx.x;
    float2 v = *(const float2*)(x + (size_t)b * Dn + 2 * t);
    *(float2*)(out + OFF_R + (size_t)b * Ln * Dn + 2 * t) = v;
    __nv_bfloat162 bv;
    bv.x = __float2bfloat16_rn(v.x);
    bv.y = __float2bfloat16_rn(v.y);
    *(__nv_bfloat162*)(g_xh + (size_t)b * Dn + 2 * t) = bv;
    float p = __fadd_rn(__fmul_rn(v.x, v.x), __fmul_rn(v.y, v.y));
    float s = xla_norm_tail(p, sh8);
    if (t == 0) g_xnorm[b] = s;
}

// ---------------- approx score GEMM + f16 store + per-block row mins ----------------
// Block 128 rows x 128 codes, 8 warps (2x4), warp tile 64x32, stages of k=32.
constexpr int KSTR = 40;   // bf16 row stride per stage (80B rows: 16B-aligned, conflict-free)

__global__ void __launch_bounds__(256, 2)
gemm_kernel(int level) {
    __shared__ __align__(16) __nv_bfloat16 as[2][128 * KSTR];  // 20 KB
    __shared__ __align__(16) __nv_bfloat16 bs[2][128 * KSTR];  // 20 KB

    const int tid = threadIdx.x;
    const int lane = tid & 31;
    const int wid = tid >> 5;
    const int warp_m = wid >> 2;       // 0..1
    const int warp_n = wid & 3;        // 0..3
    const int m0 = blockIdx.y * 128;
    const int n0 = blockIdx.x * 128;

    const __nv_bfloat16* __restrict__ Ag = g_xh + (size_t)m0 * Dn;
    const __nv_bfloat16* __restrict__ Bg = g_cbh + ((size_t)level * Kn + n0) * Dn;

    // fill: 2 chunks of 16B per matrix per thread per stage
    const int frow0 = tid >> 2, fq0 = (tid & 3) << 3;               // chunk tid
    const int frow1 = (tid + 256) >> 2, fq1 = ((tid + 256) & 3) << 3;

    // ldmatrix lane addressing (layouts proven in R9)
    const int arow = (lane & 7) + ((lane >> 3) & 1) * 8;
    const int acol = (lane >> 4) << 3;
    const int brow = lane & 7;
    const int bcol = ((lane >> 3) & 1) << 3;

    float acc[4][4][4];
#pragma unroll
    for (int i = 0; i < 4; i++)
#pragma unroll
        for (int j = 0; j < 4; j++)
#pragma unroll
            for (int r = 0; r < 4; r++) acc[i][j][r] = 0.0f;

#define FILL_STAGE(buf, ks)                                                          \
    do {                                                                             \
        cpa16(sptr(as[buf] + frow0 * KSTR + fq0), Ag + (size_t)frow0 * Dn + (ks) * 32 + fq0); \
        cpa16(sptr(as[buf] + frow1 * KSTR + fq1), Ag + (size_t)frow1 * Dn + (ks) * 32 + fq1); \
        cpa16(sptr(bs[buf] + frow0 * KSTR + fq0), Bg + (size_t)frow0 * Dn + (ks) * 32 + fq0); \
        cpa16(sptr(bs[buf] + frow1 * KSTR + fq1), Bg + (size_t)frow1 * Dn + (ks) * 32 + fq1); \
        asm volatile("cp.async.commit_group;");                                      \
    } while (0)

    FILL_STAGE(0, 0);
    asm volatile("cp.async.wait_group 0;");
    __syncthreads();

#pragma unroll 1
    for (int ks = 0; ks < 16; ks++) {
        const int cur = ks & 1;
        if (ks + 1 < 16) FILL_STAGE(cur ^ 1, ks + 1);
        // compute stage: 2 sub-steps of k16
#pragma unroll
        for (int sub = 0; sub < 2; sub++) {
            uint32_t a[4][4], bf[4][2];
#pragma unroll
            for (int mt = 0; mt < 4; mt++) {
                uint32_t ad = sptr(as[cur] + (warp_m * 64 + mt * 16 + arow) * KSTR
                                   + acol + sub * 16);
                asm volatile("ldmatrix.sync.aligned.m8n8.x4.shared.b16 {%0,%1,%2,%3}, [%4];"
                             : "=r"(a[mt][0]), "=r"(a[mt][1]), "=r"(a[mt][2]), "=r"(a[mt][3])
                             : "r"(ad));
            }
#pragma unroll
            for (int nt = 0; nt < 4; nt++) {
                uint32_t bd = sptr(bs[cur] + (warp_n * 32 + nt * 8 + brow) * KSTR
                                   + bcol + sub * 16);
                asm volatile("ldmatrix.sync.aligned.m8n8.x2.shared.b16 {%0,%1}, [%2];"
                             : "=r"(bf[nt][0]), "=r"(bf[nt][1]) : "r"(bd));
            }
#pragma unroll
            for (int mt = 0; mt < 4; mt++)
#pragma unroll
                for (int nt = 0; nt < 4; nt++) {
                    asm volatile(
                        "mma.sync.aligned.m16n8k16.row.col.f32.bf16.bf16.f32 "
                        "{%0,%1,%2,%3}, {%4,%5,%6,%7}, {%8,%9}, {%0,%1,%2,%3};"
                        : "+f"(acc[mt][nt][0]), "+f"(acc[mt][nt][1]),
                          "+f"(acc[mt][nt][2]), "+f"(acc[mt][nt][3])
                        : "r"(a[mt][0]), "r"(a[mt][1]), "r"(a[mt][2]), "r"(a[mt][3]),
                          "r"(bf[nt][0]), "r"(bf[nt][1]));
                }
        }
        if (ks + 1 < 16) asm volatile("cp.async.wait_group 0;");
        __syncthreads();
    }

    // epilogue: t~ = cn - 2m~ -> f16 store + per-row block min
    const float* __restrict__ cn = g_cnorm + level * Kn;
    const int g = lane >> 2;
    const int tq = lane & 3;
    float* smin = (float*)as;   // 128*4 floats, safe after final sync

    float rmin[8];
#pragma unroll
    for (int i = 0; i < 8; i++) rmin[i] = FLT_MAX;

#pragma unroll
    for (int mt = 0; mt < 4; mt++) {
#pragma unroll
        for (int nt = 0; nt < 4; nt++) {
            int cl = warp_n * 32 + nt * 8 + tq * 2;       // local col
            float2 cnv = *(const float2*)(cn + n0 + cl);
            int r0 = m0 + warp_m * 64 + mt * 16 + g;
            float2 o0, o1;
            o0.x = fmaf(-2.0f, acc[mt][nt][0], cnv.x);
            o0.y = fmaf(-2.0f, acc[mt][nt][1], cnv.y);
            o1.x = fmaf(-2.0f, acc[mt][nt][2], cnv.x);
            o1.y = fmaf(-2.0f, acc[mt][nt][3], cnv.y);
            *(__half2*)(g_sch + (size_t)r0 * Kn + n0 + cl) = __floats2half2_rn(o0.x, o0.y);
            *(__half2*)(g_sch + (size_t)(r0 + 8) * Kn + n0 + cl) = __floats2half2_rn(o1.x, o1.y);
            rmin[mt * 2]     = fminf(rmin[mt * 2],     fminf(o0.x, o0.y));
            rmin[mt * 2 + 1] = fminf(rmin[mt * 2 + 1], fminf(o1.x, o1.y));
        }
    }
#pragma unroll
    for (int i = 0; i < 8; i++) {
        rmin[i] = fminf(rmin[i], __shfl_xor_sync(0xFFFFFFFFu, rmin[i], 1));
        rmin[i] = fminf(rmin[i], __shfl_xor_sync(0xFFFFFFFFu, rmin[i], 2));
    }
    if (tq == 0) {
#pragma unroll
        for (int mt = 0; mt < 4; mt++) {
            smin[(warp_m * 64 + mt * 16 + g) * 4 + warp_n]     = rmin[mt * 2];
            smin[(warp_m * 64 + mt * 16 + g + 8) * 4 + warp_n] = rmin[mt * 2 + 1];
        }
    }
    __syncthreads();
    if (tid < 128) {
        float m = fminf(fminf(smin[tid * 4], smin[tid * 4 + 1]),
                        fminf(smin[tid * 4 + 2], smin[tid * 4 + 3]));
        g_bmin[(size_t)(m0 + tid) * 16 + blockIdx.x] = m;
    }
#undef FILL_STAGE
}

// ---------------- select: bmin reduce + f16 candidate collect + exact rescore ----------------
constexpr int CAP = 64;

__global__ void __launch_bounds__(256)
select_kernel(float* __restrict__ out_base, const float* __restrict__ cb, int level) {
    __shared__ int cand[8][CAP];
    const int lane = threadIdx.x & 31;
    const int wid = threadIdx.x >> 5;
    const int b = blockIdx.x * 8 + wid;

    const __half2* __restrict__ srow = (const __half2*)(g_sch + (size_t)b * Kn);
    const float* __restrict__ cnl = g_cnorm + level * Kn;
    const float* __restrict__ cbl = cb + (size_t)level * Kn * Dn;
    const float* __restrict__ xr = out_base + OFF_R + ((size_t)b * Ln + level) * Dn;
    const float xn = g_xnorm[b];

    // min over 16 block mins
    float vmin = (lane < 16) ? g_bmin[(size_t)b * 16 + lane] : FLT_MAX;
#pragma unroll
    for (int off = 16; off; off >>= 1)
        vmin = fminf(vmin, __shfl_xor_sync(0xFFFFFFFFu, vmin, off));

    // rigorous threshold: bf16 GEMM error + combine rounding (0.5) + f16 score quant (4)
    float T = vmin + 0.032f * sqrtf(xn * g_cnmax[level]) + 4.5f;

    // candidate collection (order-independent; rescore tie-breaks on k)
    int cnt = 0;
#pragma unroll 1
    for (int c = 0; c < 32; c++) {
        int j = c * 32 + lane;
        __half2 hv = srow[j];
        float f0 = __low2float(hv), f1 = __high2float(hv);
        bool p0 = (f0 <= T);
        unsigned mk = __ballot_sync(0xFFFFFFFFu, p0);
        int pos = cnt + __popc(mk & ((1u << lane) - 1u));
        if (p0 && pos < CAP) cand[wid][pos] = 2 * j;
        cnt += __popc(mk);
        bool p1 = (f1 <= T);
        mk = __ballot_sync(0xFFFFFFFFu, p1);
        pos = cnt + __popc(mk & ((1u << lane) - 1u));
        if (p1 && pos < CAP) cand[wid][pos] = 2 * j + 1;
        cnt += __popc(mk);
    }
    bool ovf = (cnt > CAP);
    int n_items = ovf ? Kn : cnt;

    // exact rescore (bitwise R3 chain)
    float bv = FLT_MAX;
    int bk = 0x7FFFFFFF;
    for (int j = lane; j < n_items; j += 32) {
        int k = ovf ? j : cand[wid][j];
        const float* cr = cbl + (size_t)k * Dn;
        float m = 0.0f;
#pragma unroll 8
        for (int d = 0; d < Dn; d++) m = __fmaf_rn(xr[d], cr[d], m);
        float v = __fadd_rn(__fsub_rn(xn, __fmul_rn(2.0f, m)), cnl[k]);
        if (v < bv || (v == bv && k < bk)) { bv = v; bk = k; }
    }
#pragma unroll
    for (int off = 16; off; off >>= 1) {
        float ov = __shfl_down_sync(0xFFFFFFFFu, bv, off);
        int ok = __shfl_down_sync(0xFFFFFFFFu, bk, off);
        if (ov < bv || (ov == bv && ok < bk)) { bv = ov; bk = ok; }
    }
    if (lane == 0) {
        g_idx[b * Ln + level] = bk;
        out_base[OFF_OUT + (size_t)b * Ln + level] = (float)bk;
        atomicAdd(&g_hist[level * Kn + bk], 1);
    }
}

// ---------------- fused update: e, next residual, bf16, next xnorm ----------------
__global__ void __launch_bounds__(256)
update_kernel(const float* __restrict__ cb, float* __restrict__ out, int level) {
    __shared__ float sh8[8];
    int b = blockIdx.x;
    int t = threadIdx.x;
    int idx = g_idx[b * Ln + level];
    const float* cr = cb + ((size_t)level * Kn + idx) * Dn;
    float2 c = *(const float2*)(cr + 2 * t);
    size_t ro = ((size_t)b * Ln + level) * Dn + 2 * t;
    *(float2*)(out + OFF_E + ro) = c;
    if (level < Ln - 1) {
        float2 r = *(const float2*)(out + OFF_R + ro);
        float2 rn;
        rn.x = __fsub_rn(r.x, c.x);
        rn.y = __fsub_rn(r.y, c.y);
        *(float2*)(out + OFF_R + ro + Dn) = rn;
        __nv_bfloat162 bv;
        bv.x = __float2bfloat16_rn(rn.x);
        bv.y = __float2bfloat16_rn(rn.y);
        *(__nv_bfloat162*)(g_xh + (size_t)b * Dn + 2 * t) = bv;
        float p = __fadd_rn(__fmul_rn(rn.x, rn.x), __fmul_rn(rn.y, rn.y));
        float s = xla_norm_tail(p, sh8);
        if (t == 0) g_xnorm[b] = s;
    }
}

// ---------------- z_hat ----------------
__global__ void zhat_kernel(const float* __restrict__ x, float* __restrict__ out) {
    size_t t = (size_t)blockIdx.x * 256 + threadIdx.x;   // B*D/4
    int b = (int)(t >> 7);
    int d4 = ((int)t & 127) << 2;
    const float* eb = out + OFF_E + (size_t)b * Ln * Dn + d4;
    float4 e0 = *(const float4*)(eb);
    float4 e1 = *(const float4*)(eb + Dn);
    float4 e2 = *(const float4*)(eb + 2 * Dn);
    float4 e3 = *(const float4*)(eb + 3 * Dn);
    float4 xv = *(const float4*)(x + (size_t)b * Dn + d4);
    float4 z;
    z.x = __fadd_rn(xv.x, __fsub_rn(__fadd_rn(__fadd_rn(__fadd_rn(e0.x, e1.x), e2.x), e3.x), xv.x));
    z.y = __fadd_rn(xv.y, __fsub_rn(__fadd_rn(__fadd_rn(__fadd_rn(e0.y, e1.y), e2.y), e3.y), xv.y));
    z.z = __fadd_rn(xv.z, __fsub_rn(__fadd_rn(__fadd_rn(__fadd_rn(e0.z, e1.z), e2.z), e3.z), xv.z));
    z.w = __fadd_rn(xv.w, __fsub_rn(__fadd_rn(__fadd_rn(__fadd_rn(e0.w, e1.w), e2.w), e3.w), xv.w));
    *(float4*)(out + OFF_Z + (size_t)b * Dn + d4) = z;
}

// ---------------- unused-code count ----------------
__global__ void count_kernel(float* __restrict__ out) {
    int t = threadIdx.x;   // 256
    int c = 0;
    for (int i = t; i < Ln * Kn; i += 256)
        if (g_hist[i] == 0) c++;
    for (int o = 16; o; o >>= 1) c += __shfl_down_sync(0xFFFFFFFFu, c, o);
    __shared__ int ws[8];
    if ((t & 31) == 0) ws[t >> 5] = c;
    __syncthreads();
    if (t == 0) {
        int tot = 0;
        for (int j = 0; j < 8; j++) tot += ws[j];
        out[OFF_CNT] = (float)tot;
    }
}

extern "C" void kernel_launch(void* const* d_in, const int* in_sizes, int n_in,
                              void* d_out, int out_size) {
    const float* x  = (const float*)d_in[0];   // [B, D]
    const float* cb = (const float*)d_in[1];   // [L, K, D]
    float* out = (float*)d_out;

    init_kernel<<<1, 32>>>();
    prep_kernel<<<Ln * Kn, 256>>>(cb);
    copy_r0_kernel<<<Bn, 256>>>(x, out);
    for (int l = 0; l < Ln; l++) {
        gemm_kernel<<<dim3(Kn / 128, Bn / 128), 256>>>(l);
        select_kernel<<<Bn / 8, 256>>>(out, cb, l);
        update_kernel<<<Bn, 256>>>(cb, out, l);
    }
    zhat_kernel<<<(Bn * Dn / 4) / 256, 256>>>(x, out);
    count_kernel<<<1, 256>>>(out);
}